// round 6
// baseline (speedup 1.0000x reference)
#include <cuda_runtime.h>
#include <math.h>

#define DD 256
#define KK 32
#define QQ 16
#define NN 8192

// Scratch (device globals: no allocation allowed in kernel_launch)
__device__ float g_B[DD * KK * QQ];   // [d][k*16+q] = G_k[d][q]
__device__ float g_H[DD * KK];        // [d][k] = inv_psi[d]*mu[k][d]
__device__ float g_c[KK * QQ];        // c_k = G_k^T mu_k
__device__ float g_Ck[KK];            // per-k constant
__device__ float g_ip[DD];            // inv_psi
__device__ float g_P[NN * KK];        // ||G^T x - c||^2

__device__ __forceinline__ float warp_sum(float v) {
    v += __shfl_xor_sync(0xffffffffu, v, 16);
    v += __shfl_xor_sync(0xffffffffu, v, 8);
    v += __shfl_xor_sync(0xffffffffu, v, 4);
    v += __shfl_xor_sync(0xffffffffu, v, 2);
    v += __shfl_xor_sync(0xffffffffu, v, 1);
    return v;
}

__device__ __forceinline__ float warp_max(float v) {
    v = fmaxf(v, __shfl_xor_sync(0xffffffffu, v, 16));
    v = fmaxf(v, __shfl_xor_sync(0xffffffffu, v, 8));
    v = fmaxf(v, __shfl_xor_sync(0xffffffffu, v, 4));
    v = fmaxf(v, __shfl_xor_sync(0xffffffffu, v, 2));
    v = fmaxf(v, __shfl_xor_sync(0xffffffffu, v, 1));
    return v;
}

// ---------------------------------------------------------------------------
// Setup: one block per mixture component k.
// Builds M = I + Lam^T Psi^-1 Lam (16x16), Cholesky, G = Psi^-1 Lam L^-T,
// h = Psi^-1 mu, c = G^T mu, and the scalar constant C_k.
// ---------------------------------------------------------------------------
__global__ void __launch_bounds__(256) setup_kernel(
    const float* __restrict__ log_pi,
    const float* __restrict__ mu,
    const float* __restrict__ Lambda,
    const float* __restrict__ log_psi)
{
    __shared__ float Ls[DD][QQ + 1];     // Lambda_k staged
    __shared__ float ip_s[DD];
    __shared__ float Msm[QQ][QQ + 1];
    __shared__ float Lch[QQ][QQ + 1];
    __shared__ float c_s[QQ];
    __shared__ float s_mdm;
    __shared__ float s_ldpsi;
    __shared__ float s_ldM;

    const int k = blockIdx.x;
    const int t = threadIdx.x;           // t == d for per-dimension work
    const int lane = t & 31;

    // inv_psi and log-psi (diag of C is psi + 1e-5, psi = exp(log_psi)+1e-6)
    float psi = expf(log_psi[t]) + 1e-6f + 1e-5f;
    float ip = 1.0f / psi;
    ip_s[t] = ip;

    if (t == 0) { s_mdm = 0.f; s_ldpsi = 0.f; }
    if (t < QQ) c_s[t] = 0.f;

    // Stage Lambda_k row d = t (16 floats, vectorized)
    {
        const float4* lp = reinterpret_cast<const float4*>(Lambda + ((size_t)k * DD + t) * QQ);
        float4 v0 = lp[0], v1 = lp[1], v2 = lp[2], v3 = lp[3];
        Ls[t][0] = v0.x;  Ls[t][1] = v0.y;  Ls[t][2] = v0.z;  Ls[t][3] = v0.w;
        Ls[t][4] = v1.x;  Ls[t][5] = v1.y;  Ls[t][6] = v1.z;  Ls[t][7] = v1.w;
        Ls[t][8] = v2.x;  Ls[t][9] = v2.y;  Ls[t][10] = v2.z; Ls[t][11] = v2.w;
        Ls[t][12] = v3.x; Ls[t][13] = v3.y; Ls[t][14] = v3.z; Ls[t][15] = v3.w;
    }
    __syncthreads();

    // logdet(Psi) reduction
    {
        float v = warp_sum(logf(psi));
        if (lane == 0) atomicAdd(&s_ldpsi, v);
    }

    // M[q1][q2] = sum_d Ls[d][q1]*ip[d]*Ls[d][q2]  (+ I)
    {
        int q1 = t >> 4, q2 = t & 15;
        float s = 0.f;
        #pragma unroll 8
        for (int d = 0; d < DD; d++)
            s = fmaf(Ls[d][q1] * ip_s[d], Ls[d][q2], s);
        Msm[q1][q2] = s + (q1 == q2 ? 1.0f : 0.0f);
    }
    __syncthreads();

    // Cholesky of M (16x16, serial on thread 0 — negligible work)
    if (t == 0) {
        float ld = 0.f;
        for (int j = 0; j < QQ; j++) {
            float s = Msm[j][j];
            for (int p = 0; p < j; p++) s -= Lch[j][p] * Lch[j][p];
            float ljj = sqrtf(s);
            Lch[j][j] = ljj;
            ld += logf(ljj);
            float inv = 1.0f / ljj;
            for (int i = j + 1; i < QQ; i++) {
                float v = Msm[i][j];
                for (int p = 0; p < j; p++) v -= Lch[i][p] * Lch[j][p];
                Lch[i][j] = v * inv;
            }
        }
        s_ldM = 2.0f * ld;   // logdet(M)
    }
    __syncthreads();

    // Row d of G: forward solve L g = ip[d] * Lambda[d,:]
    {
        float g[QQ];
        #pragma unroll
        for (int i = 0; i < QQ; i++) {
            float v = ip * Ls[t][i];
            #pragma unroll
            for (int p = 0; p < QQ; p++)
                if (p < i) v -= Lch[i][p] * g[p];
            g[i] = v / Lch[i][i];
        }
        float mud = mu[(size_t)k * DD + t];
        #pragma unroll
        for (int i = 0; i < QQ; i++)
            g_B[(size_t)t * (KK * QQ) + k * QQ + i] = g[i];
        g_H[(size_t)t * KK + k] = ip * mud;
        if (k == 0) g_ip[t] = ip;

        // c = G^T mu and mu^T Psi^-1 mu (warp reduce + smem atomic)
        #pragma unroll
        for (int i = 0; i < QQ; i++) {
            float v = warp_sum(g[i] * mud);
            if (lane == 0) atomicAdd(&c_s[i], v);
        }
        float vm = warp_sum(ip * mud * mud);
        if (lane == 0) atomicAdd(&s_mdm, vm);
    }
    __syncthreads();

    if (t < QQ) g_c[k * QQ + t] = c_s[t];
    if (t == 0) {
        const float LOG2PI = 1.8378770664093453f;
        g_Ck[k] = log_pi[k] - 0.5f * ((float)DD * LOG2PI + s_ldpsi + s_ldM + s_mdm);
    }
}

// ---------------------------------------------------------------------------
// Main GEMM: U = X[8192,256] @ G[256,512], fused epilogue reduces the 16
// columns of each k to P[n][k] = ||u - c_k||^2.
// Block tile 128 rows x 64 cols (4 k's), 256 threads, thread tile 8x4.
// ---------------------------------------------------------------------------
__global__ void __launch_bounds__(256) gemm_kernel(const float* __restrict__ X)
{
    __shared__ __align__(16) float As[16][132];   // A chunk, transposed [kk][row]
    __shared__ __align__(16) float Bs[16][68];    // B chunk [kk][col]

    const int rowBase = blockIdx.x * 128;
    const int colBase = blockIdx.y * 64;
    const int tid = threadIdx.x;
    const int tc = tid & 15;
    const int tr = tid >> 4;

    float acc[8][4];
    #pragma unroll
    for (int i = 0; i < 8; i++)
        #pragma unroll
        for (int j = 0; j < 4; j++) acc[i][j] = 0.f;

    for (int d0 = 0; d0 < DD; d0 += 16) {
        // Load A tile (128 rows x 16 d), store transposed
        #pragma unroll
        for (int i2 = 0; i2 < 2; i2++) {
            int r = (tid >> 2) + i2 * 64;
            int q4 = (tid & 3) * 4;
            float4 v = *reinterpret_cast<const float4*>(
                &X[(size_t)(rowBase + r) * DD + d0 + q4]);
            As[q4 + 0][r] = v.x;
            As[q4 + 1][r] = v.y;
            As[q4 + 2][r] = v.z;
            As[q4 + 3][r] = v.w;
        }
        // Load B tile (16 d x 64 cols)
        {
            int d = tid >> 4, cg = (tid & 15) * 4;
            float4 v = *reinterpret_cast<const float4*>(
                &g_B[(size_t)(d0 + d) * (KK * QQ) + colBase + cg]);
            *reinterpret_cast<float4*>(&Bs[d][cg]) = v;
        }
        __syncthreads();

        #pragma unroll
        for (int kk = 0; kk < 16; kk++) {
            float4 a0 = *reinterpret_cast<float4*>(&As[kk][tr * 8]);
            float4 a1 = *reinterpret_cast<float4*>(&As[kk][tr * 8 + 4]);
            float4 bb = *reinterpret_cast<float4*>(&Bs[kk][tc * 4]);
            float a[8] = {a0.x, a0.y, a0.z, a0.w, a1.x, a1.y, a1.z, a1.w};
            float b[4] = {bb.x, bb.y, bb.z, bb.w};
            #pragma unroll
            for (int i = 0; i < 8; i++)
                #pragma unroll
                for (int j = 0; j < 4; j++)
                    acc[i][j] = fmaf(a[i], b[j], acc[i][j]);
        }
        __syncthreads();
    }

    // Epilogue: this thread's 4 cols live inside one k; reduce ||u-c||^2
    const int kg = (colBase >> 4) + (tc >> 2);     // global k
    const int qb = (tc & 3) * 4;                   // first q of this thread
    const float c0 = g_c[kg * QQ + qb + 0];
    const float c1 = g_c[kg * QQ + qb + 1];
    const float c2 = g_c[kg * QQ + qb + 2];
    const float c3 = g_c[kg * QQ + qb + 3];

    #pragma unroll
    for (int i = 0; i < 8; i++) {
        float e0 = acc[i][0] - c0;
        float e1 = acc[i][1] - c1;
        float e2 = acc[i][2] - c2;
        float e3 = acc[i][3] - c3;
        float pv = e0 * e0 + e1 * e1 + e2 * e2 + e3 * e3;
        // The 4 threads sharing (row, k) are consecutive lanes (tc%4 groups)
        pv += __shfl_xor_sync(0xffffffffu, pv, 1);
        pv += __shfl_xor_sync(0xffffffffu, pv, 2);
        if ((tc & 3) == 0)
            g_P[(size_t)(rowBase + tr * 8 + i) * KK + kg] = pv;
    }
}

// ---------------------------------------------------------------------------
// Epilogue: per row n, compute hx[k] = h_k^T x, xdx = x^T Psi^-1 x,
// combine with P and C_k, log-softmax over k=32 (one lane per k).
// One warp per row; 8 warps/block; 64 rows/block.
// ---------------------------------------------------------------------------
__global__ void __launch_bounds__(256) epi_kernel(
    const float* __restrict__ X, float* __restrict__ out)
{
    __shared__ float Hs[DD][KK + 1];   // 33.8 KB
    __shared__ float Cks[KK];
    __shared__ float ips[DD];
    __shared__ float Xs[8][DD];

    const int tid = threadIdx.x;
    const int w = tid >> 5;
    const int lane = tid & 31;

    for (int i = tid; i < DD * KK; i += 256)
        Hs[i >> 5][i & 31] = g_H[i];
    if (tid < KK) Cks[tid] = g_Ck[tid];
    ips[tid] = g_ip[tid];
    __syncthreads();

    #pragma unroll 1
    for (int it = 0; it < 8; it++) {
        int n = blockIdx.x * 64 + it * 8 + w;

        float xdx = 0.f;
        #pragma unroll
        for (int j = 0; j < 8; j++) {
            float v = X[(size_t)n * DD + j * 32 + lane];
            Xs[w][j * 32 + lane] = v;
            xdx = fmaf(ips[j * 32 + lane] * v, v, xdx);
        }
        xdx = warp_sum(xdx);
        __syncwarp();

        float hx = 0.f;
        #pragma unroll 16
        for (int d = 0; d < DD; d++)
            hx = fmaf(Xs[w][d], Hs[d][lane], hx);

        float val = Cks[lane] + hx + 0.5f * g_P[(size_t)n * KK + lane] - 0.5f * xdx;

        // log-softmax over the 32 lanes
        float m = warp_max(val);
        float s = warp_sum(expf(val - m));
        float lse = m + logf(s);

        out[(size_t)n * KK + lane] = val - lse;
        if (lane == 0) out[(size_t)NN * KK + n] = lse;
        __syncwarp();
    }
}

extern "C" void kernel_launch(void* const* d_in, const int* in_sizes, int n_in,
                              void* d_out, int out_size)
{
    const float* X       = (const float*)d_in[0];
    const float* log_pi  = (const float*)d_in[1];
    const float* mu      = (const float*)d_in[2];
    const float* Lambda  = (const float*)d_in[3];
    const float* log_psi = (const float*)d_in[4];
    float* out = (float*)d_out;

    setup_kernel<<<KK, 256>>>(log_pi, mu, Lambda, log_psi);
    gemm_kernel<<<dim3(NN / 128, (KK * QQ) / 64), 256>>>(X);
    epi_kernel<<<NN / 64, 256>>>(X, out);
}

// round 8
// speedup vs baseline: 1.4145x; 1.4145x over previous
#include <cuda_runtime.h>
#include <math.h>

#define DD 256
#define KK 32
#define QQ 16
#define NN 8192

// Scratch (device globals: no allocation allowed in kernel_launch)
__device__ float g_B[DD * KK * QQ];   // [d][k*16+q] = G_k[d][q]
__device__ float g_H[DD * KK];        // [d][k] = inv_psi[d]*mu[k][d]
__device__ float g_c[KK * QQ];        // c_k = G_k^T mu_k
__device__ float g_Ck[KK];            // per-k constant
__device__ float g_ip[DD];            // inv_psi
__device__ float g_P[NN * KK];        // ||G^T x - c||^2
__device__ float g_HX[NN * KK];       // h_k^T x

// ---- packed f32x2 helpers (Blackwell 2x fp32 pipe) ----
#define FMA2(acc, a, b) \
    asm("fma.rn.f32x2 %0, %1, %2, %0;" : "+l"(acc) : "l"(a), "l"(b))
#define MUL2(d, a, b) \
    asm("mul.rn.f32x2 %0, %1, %2;" : "=l"(d) : "l"(a), "l"(b))
#define PACKDUP(d, f) \
    asm("mov.b64 %0, {%1, %1};" : "=l"(d) : "r"(__float_as_uint(f)))
#define PACK2(d, flo, fhi) \
    asm("mov.b64 %0, {%1, %2};" : "=l"(d) : "r"(__float_as_uint(flo)), "r"(__float_as_uint(fhi)))
#define UNPACK2(flo, fhi, v) do { unsigned _lo, _hi; \
    asm("mov.b64 {%0, %1}, %2;" : "=r"(_lo), "=r"(_hi) : "l"(v)); \
    flo = __uint_as_float(_lo); fhi = __uint_as_float(_hi); } while (0)

__device__ __forceinline__ float warp_sum(float v) {
    v += __shfl_xor_sync(0xffffffffu, v, 16);
    v += __shfl_xor_sync(0xffffffffu, v, 8);
    v += __shfl_xor_sync(0xffffffffu, v, 4);
    v += __shfl_xor_sync(0xffffffffu, v, 2);
    v += __shfl_xor_sync(0xffffffffu, v, 1);
    return v;
}

__device__ __forceinline__ float warp_max(float v) {
    v = fmaxf(v, __shfl_xor_sync(0xffffffffu, v, 16));
    v = fmaxf(v, __shfl_xor_sync(0xffffffffu, v, 8));
    v = fmaxf(v, __shfl_xor_sync(0xffffffffu, v, 4));
    v = fmaxf(v, __shfl_xor_sync(0xffffffffu, v, 2));
    v = fmaxf(v, __shfl_xor_sync(0xffffffffu, v, 1));
    return v;
}

// ---------------------------------------------------------------------------
// Setup: one block per mixture component k. Latency-optimized:
//  - 4-way split accumulators in the M build
//  - warp-parallel shfl-based Cholesky (rsqrt, no serial thread-0 loop)
//  - reciprocal-multiply forward solve (no fp32 division chains)
//  - fast-math intrinsics (__expf/__logf); error << 1e-3 budget
// ---------------------------------------------------------------------------
__global__ void __launch_bounds__(256) setup_kernel(
    const float* __restrict__ log_pi,
    const float* __restrict__ mu,
    const float* __restrict__ Lambda,
    const float* __restrict__ log_psi)
{
    __shared__ float Ls[DD][QQ + 1];     // Lambda_k
    __shared__ float LsW[DD][QQ + 1];    // inv_psi * Lambda_k
    __shared__ float Msm[QQ][QQ + 1];
    __shared__ float Lch[QQ][QQ + 1];
    __shared__ float invd_s[QQ];
    __shared__ float c_s[QQ];
    __shared__ float s_mdm;
    __shared__ float s_ldpsi;
    __shared__ float s_ldM;

    const int k = blockIdx.x;
    const int t = threadIdx.x;           // t == d for per-dimension work
    const int lane = t & 31;
    const int w = t >> 5;

    float psi = __expf(log_psi[t]) + 1e-6f + 1e-5f;
    float ip = 1.0f / psi;

    if (t == 0) { s_mdm = 0.f; s_ldpsi = 0.f; }
    if (t < QQ) c_s[t] = 0.f;

    // Stage Lambda_k row d = t, plus the inv_psi-weighted copy
    {
        const float4* lp = reinterpret_cast<const float4*>(Lambda + ((size_t)k * DD + t) * QQ);
        float4 v0 = lp[0], v1 = lp[1], v2 = lp[2], v3 = lp[3];
        float vv[QQ] = {v0.x,v0.y,v0.z,v0.w, v1.x,v1.y,v1.z,v1.w,
                        v2.x,v2.y,v2.z,v2.w, v3.x,v3.y,v3.z,v3.w};
        #pragma unroll
        for (int i = 0; i < QQ; i++) {
            Ls[t][i]  = vv[i];
            LsW[t][i] = ip * vv[i];
        }
    }
    __syncthreads();

    // logdet(Psi) reduction
    {
        float v = warp_sum(__logf(psi));
        if (lane == 0) atomicAdd(&s_ldpsi, v);
    }

    // M[q1][q2] = I + sum_d LsW[d][q1]*Ls[d][q2], 4 independent chains
    {
        int q1 = t >> 4, q2 = t & 15;
        float s0 = 0.f, s1 = 0.f, s2 = 0.f, s3 = 0.f;
        #pragma unroll 4
        for (int d = 0; d < DD; d += 4) {
            s0 = fmaf(LsW[d + 0][q1], Ls[d + 0][q2], s0);
            s1 = fmaf(LsW[d + 1][q1], Ls[d + 1][q2], s1);
            s2 = fmaf(LsW[d + 2][q1], Ls[d + 2][q2], s2);
            s3 = fmaf(LsW[d + 3][q1], Ls[d + 3][q2], s3);
        }
        Msm[q1][q2] = (s0 + s1) + (s2 + s3) + (q1 == q2 ? 1.0f : 0.0f);
    }
    __syncthreads();

    // Warp-parallel Cholesky of M (16x16): lane i owns row i, shfl broadcasts
    if (w == 0) {
        float W[QQ];
        #pragma unroll
        for (int j = 0; j < QQ; j++) W[j] = (lane < QQ) ? Msm[lane][j] : 0.f;
        float myd = 1.0f;   // lane j captures L_jj; others stay 1 -> log = 0
        #pragma unroll
        for (int j = 0; j < QQ; j++) {
            float pivot = __shfl_sync(0xffffffffu, W[j], j);
            float rs = rsqrtf(pivot);
            float ljj = pivot * rs;
            float lij;
            if (lane == j)                   { lij = ljj; myd = ljj; invd_s[j] = rs; }
            else if (lane > j && lane < QQ)  { lij = W[j] * rs; }
            else                             { lij = 0.f; }
            if (lane < QQ) Lch[lane][j] = lij;
            #pragma unroll
            for (int p = j + 1; p < QQ; p++) {
                float lpj = __shfl_sync(0xffffffffu, lij, p);
                W[p] = fmaf(-lij, lpj, W[p]);
            }
        }
        float ldm = warp_sum(__logf(myd));
        if (lane == 0) s_ldM = 2.0f * ldm;
    }
    __syncthreads();

    // Row d of G: forward solve L g = ip[d]*Lambda[d,:]  (multiply by 1/L_ii)
    {
        float g[QQ];
        #pragma unroll
        for (int i = 0; i < QQ; i++) {
            float v = LsW[t][i];
            #pragma unroll
            for (int p = 0; p < QQ; p++)
                if (p < i) v = fmaf(-Lch[i][p], g[p], v);
            g[i] = v * invd_s[i];
        }
        float mud = mu[(size_t)k * DD + t];
        #pragma unroll
        for (int i = 0; i < QQ; i++)
            g_B[(size_t)t * (KK * QQ) + k * QQ + i] = g[i];
        g_H[(size_t)t * KK + k] = ip * mud;
        if (k == 0) g_ip[t] = ip;

        #pragma unroll
        for (int i = 0; i < QQ; i++) {
            float v = warp_sum(g[i] * mud);
            if (lane == 0) atomicAdd(&c_s[i], v);
        }
        float vm = warp_sum(ip * mud * mud);
        if (lane == 0) atomicAdd(&s_mdm, vm);
    }
    __syncthreads();

    if (t < QQ) g_c[k * QQ + t] = c_s[t];
    if (t == 0) {
        const float LOG2PI = 1.8378770664093453f;
        g_Ck[k] = log_pi[k] - 0.5f * ((float)DD * LOG2PI + s_ldpsi + s_ldM + s_mdm);
    }
}

// ---------------------------------------------------------------------------
// Main GEMM with packed f32x2 FMAs: U = X[8192,256] @ [G | H | 0][256,576].
// Block tile 128 rows x 64 cols, 256 threads, thread tile (4 row-pairs) x 4.
// blockIdx.y < 8: G columns -> fused ||u - c_k||^2 into g_P.
// blockIdx.y == 8: H columns (32) + zero pad -> hx into g_HX.
// ---------------------------------------------------------------------------
__global__ void __launch_bounds__(256) gemm_kernel(const float* __restrict__ X)
{
    __shared__ __align__(16) float As[16][132];   // A chunk, transposed [kk][row]
    __shared__ __align__(16) float Bs[16][68];    // B chunk [kk][col]

    const int rowBase = blockIdx.x * 128;
    const int colBase = blockIdx.y * 64;
    const int tid = threadIdx.x;
    const int tc = tid & 15;
    const int tr = tid >> 4;

    unsigned long long acc2[4][4];
    #pragma unroll
    for (int i = 0; i < 4; i++)
        #pragma unroll
        for (int j = 0; j < 4; j++) acc2[i][j] = 0ULL;

    for (int d0 = 0; d0 < DD; d0 += 16) {
        // Load A tile (128 rows x 16 d), store transposed
        #pragma unroll
        for (int i2 = 0; i2 < 2; i2++) {
            int r = (tid >> 2) + i2 * 64;
            int q4 = (tid & 3) * 4;
            float4 v = *reinterpret_cast<const float4*>(
                &X[(size_t)(rowBase + r) * DD + d0 + q4]);
            As[q4 + 0][r] = v.x;
            As[q4 + 1][r] = v.y;
            As[q4 + 2][r] = v.z;
            As[q4 + 3][r] = v.w;
        }
        // Load B tile (16 d x 64 cols): G block, or H block + zero pad
        {
            int d = tid >> 4, cg = (tid & 15) * 4;
            float4 v;
            if (colBase < KK * QQ) {
                v = *reinterpret_cast<const float4*>(
                    &g_B[(size_t)(d0 + d) * (KK * QQ) + colBase + cg]);
            } else if (cg < KK) {
                v = *reinterpret_cast<const float4*>(
                    &g_H[(size_t)(d0 + d) * KK + cg]);
            } else {
                v = make_float4(0.f, 0.f, 0.f, 0.f);
            }
            *reinterpret_cast<float4*>(&Bs[d][cg]) = v;
        }
        __syncthreads();

        #pragma unroll
        for (int kk = 0; kk < 16; kk++) {
            unsigned long long a2[4];
            const unsigned long long* ap =
                reinterpret_cast<const unsigned long long*>(&As[kk][tr * 8]);
            a2[0] = ap[0]; a2[1] = ap[1]; a2[2] = ap[2]; a2[3] = ap[3];
            float4 bb = *reinterpret_cast<float4*>(&Bs[kk][tc * 4]);
            unsigned long long b2[4];
            PACKDUP(b2[0], bb.x);
            PACKDUP(b2[1], bb.y);
            PACKDUP(b2[2], bb.z);
            PACKDUP(b2[3], bb.w);
            #pragma unroll
            for (int i = 0; i < 4; i++)
                #pragma unroll
                for (int j = 0; j < 4; j++)
                    FMA2(acc2[i][j], a2[i], b2[j]);
        }
        __syncthreads();
    }

    if (colBase < KK * QQ) {
        // ||u - c_k||^2 path: this thread's 4 cols live inside one k
        const int kg = (colBase >> 4) + (tc >> 2);
        const int qb = (tc & 3) * 4;
        float c[4];
        #pragma unroll
        for (int j = 0; j < 4; j++) c[j] = g_c[kg * QQ + qb + j];

        #pragma unroll
        for (int i = 0; i < 4; i++) {
            float pv0 = 0.f, pv1 = 0.f;
            #pragma unroll
            for (int j = 0; j < 4; j++) {
                float lo, hi;
                UNPACK2(lo, hi, acc2[i][j]);
                float e0 = lo - c[j], e1 = hi - c[j];
                pv0 = fmaf(e0, e0, pv0);
                pv1 = fmaf(e1, e1, pv1);
            }
            pv0 += __shfl_xor_sync(0xffffffffu, pv0, 1);
            pv0 += __shfl_xor_sync(0xffffffffu, pv0, 2);
            pv1 += __shfl_xor_sync(0xffffffffu, pv1, 1);
            pv1 += __shfl_xor_sync(0xffffffffu, pv1, 2);
            if ((tc & 3) == 0) {
                int r = rowBase + tr * 8 + 2 * i;
                g_P[(size_t)r * KK + kg] = pv0;
                g_P[(size_t)(r + 1) * KK + kg] = pv1;
            }
        }
    } else if (tc < 8) {
        // hx path: cols 0..31 of this block are the K columns of H
        const int col = tc * 4;
        #pragma unroll
        for (int i = 0; i < 4; i++) {
            int r = rowBase + tr * 8 + 2 * i;
            #pragma unroll
            for (int j = 0; j < 4; j++) {
                float lo, hi;
                UNPACK2(lo, hi, acc2[i][j]);
                g_HX[(size_t)r * KK + col + j] = lo;
                g_HX[(size_t)(r + 1) * KK + col + j] = hi;
            }
        }
    }
}

// ---------------------------------------------------------------------------
// Epilogue: per row n, xdx = x^T Psi^-1 x (f32x2), combine with precomputed
// P and HX, log-softmax over k=32 (one lane per k). One warp per row.
// ---------------------------------------------------------------------------
__global__ void __launch_bounds__(256) epi_kernel(
    const float* __restrict__ X, float* __restrict__ out)
{
    __shared__ float Cks[KK];
    __shared__ unsigned long long ips2[DD / 2];

    const int tid = threadIdx.x;
    const int w = tid >> 5;
    const int lane = tid & 31;

    if (tid < KK) Cks[tid] = g_Ck[tid];
    if (tid < DD / 2) {
        unsigned long long p;
        PACK2(p, g_ip[2 * tid], g_ip[2 * tid + 1]);
        ips2[tid] = p;
    }
    __syncthreads();

    #pragma unroll 1
    for (int it = 0; it < 8; it++) {
        int n = blockIdx.x * 64 + it * 8 + w;

        unsigned long long xdx2 = 0ULL;
        #pragma unroll
        for (int j = 0; j < 4; j++) {
            int m = j * 32 + lane;
            unsigned long long xp = *reinterpret_cast<const unsigned long long*>(
                &X[(size_t)n * DD + 2 * m]);
            unsigned long long t2;
            MUL2(t2, ips2[m], xp);
            FMA2(xdx2, t2, xp);
        }
        float xlo, xhi;
        UNPACK2(xlo, xhi, xdx2);
        float xdx = warp_sum(xlo + xhi);

        float val = Cks[lane] + g_HX[(size_t)n * KK + lane]
                  + 0.5f * g_P[(size_t)n * KK + lane] - 0.5f * xdx;

        // log-softmax over the 32 lanes
        float m = warp_max(val);
        float s = warp_sum(__expf(val - m));
        float lse = m + __logf(s);

        out[(size_t)n * KK + lane] = val - lse;
        if (lane == 0) out[(size_t)NN * KK + n] = lse;
        __syncwarp();
    }
}

extern "C" void kernel_launch(void* const* d_in, const int* in_sizes, int n_in,
                              void* d_out, int out_size)
{
    const float* X       = (const float*)d_in[0];
    const float* log_pi  = (const float*)d_in[1];
    const float* mu      = (const float*)d_in[2];
    const float* Lambda  = (const float*)d_in[3];
    const float* log_psi = (const float*)d_in[4];
    float* out = (float*)d_out;

    setup_kernel<<<KK, 256>>>(log_pi, mu, Lambda, log_psi);
    gemm_kernel<<<dim3(NN / 128, (KK * QQ) / 64 + 1), 256>>>(X);
    epi_kernel<<<NN / 64, 256>>>(X, out);
}

// round 11
// speedup vs baseline: 1.6946x; 1.1980x over previous
#include <stdint.h>
#include <cstdint>
#include <cuda_runtime.h>
#include <cuda_bf16.h>
#include <math.h>

#define DD 256
#define KK 32
#define QQ 16
#define NN 8192
#define NCOL 640          // 512 G cols + 32 H cols + 96 zero pad (5 tiles of 128)

// Scratch (device globals: no allocation allowed in kernel_launch)
__device__ float g_c[KK * QQ];            // c_k = G_k^T mu_k
__device__ float g_Ck[KK];                // per-k constant
__device__ float g_ip[DD];                // inv_psi
__device__ float g_P[NN * KK];            // ||G^T x - c||^2
__device__ float g_HX[NN * KK];           // h_k^T x
__device__ __align__(16) __nv_bfloat16 g_Xh[NN * DD];
__device__ __align__(16) __nv_bfloat16 g_Xl[NN * DD];
__device__ __align__(16) __nv_bfloat16 g_Bh[NCOL * DD];   // [col][d]; rows 544+ stay zero
__device__ __align__(16) __nv_bfloat16 g_Bl[NCOL * DD];

// ---- packed f32x2 helpers ----
#define FMA2(acc, a, b) \
    asm("fma.rn.f32x2 %0, %1, %2, %0;" : "+l"(acc) : "l"(a), "l"(b))
#define MUL2(d, a, b) \
    asm("mul.rn.f32x2 %0, %1, %2;" : "=l"(d) : "l"(a), "l"(b))
#define PACK2(d, flo, fhi) \
    asm("mov.b64 %0, {%1, %2};" : "=l"(d) : "r"(__float_as_uint(flo)), "r"(__float_as_uint(fhi)))
#define UNPACK2(flo, fhi, v) do { unsigned _lo, _hi; \
    asm("mov.b64 {%0, %1}, %2;" : "=r"(_lo), "=r"(_hi) : "l"(v)); \
    flo = __uint_as_float(_lo); fhi = __uint_as_float(_hi); } while (0)

__device__ __forceinline__ uint32_t smem_u32(const void* p) {
    uint32_t a;
    asm("{ .reg .u64 t; cvta.to.shared.u64 t, %1; cvt.u32.u64 %0, t; }" : "=r"(a) : "l"(p));
    return a;
}

// ldmatrix x4 (baseline PTX, sm_75+)
#define LDM_X4(r, addr) \
    asm volatile("ldmatrix.sync.aligned.m8n8.x4.shared.b16 {%0,%1,%2,%3}, [%4];" \
        : "=r"((r)[0]), "=r"((r)[1]), "=r"((r)[2]), "=r"((r)[3]) : "r"(addr))

// mma.sync bf16 (baseline PTX, sm_80+) — runs on tensor pipe (HMMA)
__device__ __forceinline__ void mma_bf16(float* c, const uint32_t* a, const uint32_t* b) {
    asm volatile(
        "mma.sync.aligned.m16n8k16.row.col.f32.bf16.bf16.f32 "
        "{%0,%1,%2,%3}, {%4,%5,%6,%7}, {%8,%9}, {%0,%1,%2,%3};"
        : "+f"(c[0]), "+f"(c[1]), "+f"(c[2]), "+f"(c[3])
        : "r"(a[0]), "r"(a[1]), "r"(a[2]), "r"(a[3]), "r"(b[0]), "r"(b[1]));
}

__device__ __forceinline__ float warp_sum(float v) {
    v += __shfl_xor_sync(0xffffffffu, v, 16);
    v += __shfl_xor_sync(0xffffffffu, v, 8);
    v += __shfl_xor_sync(0xffffffffu, v, 4);
    v += __shfl_xor_sync(0xffffffffu, v, 2);
    v += __shfl_xor_sync(0xffffffffu, v, 1);
    return v;
}
__device__ __forceinline__ float warp_max(float v) {
    v = fmaxf(v, __shfl_xor_sync(0xffffffffu, v, 16));
    v = fmaxf(v, __shfl_xor_sync(0xffffffffu, v, 8));
    v = fmaxf(v, __shfl_xor_sync(0xffffffffu, v, 4));
    v = fmaxf(v, __shfl_xor_sync(0xffffffffu, v, 2));
    v = fmaxf(v, __shfl_xor_sync(0xffffffffu, v, 1));
    return v;
}

// ---------------------------------------------------------------------------
// X convert: fp32 -> bf16 hi/lo split.
// ---------------------------------------------------------------------------
__global__ void __launch_bounds__(256) convx_kernel(const float* __restrict__ X)
{
    int i = (blockIdx.x * 256 + threadIdx.x) * 8;
    float4 a = *reinterpret_cast<const float4*>(X + i);
    float4 b = *reinterpret_cast<const float4*>(X + i + 4);
    float v[8] = {a.x, a.y, a.z, a.w, b.x, b.y, b.z, b.w};
    uint32_t ph[4], pl[4];
    #pragma unroll
    for (int j = 0; j < 4; j++) {
        __nv_bfloat16 h0 = __float2bfloat16(v[2 * j]);
        __nv_bfloat16 h1 = __float2bfloat16(v[2 * j + 1]);
        __nv_bfloat16 l0 = __float2bfloat16(v[2 * j] - __bfloat162float(h0));
        __nv_bfloat16 l1 = __float2bfloat16(v[2 * j + 1] - __bfloat162float(h1));
        ph[j] = (uint32_t)__bfloat16_as_ushort(h0) | ((uint32_t)__bfloat16_as_ushort(h1) << 16);
        pl[j] = (uint32_t)__bfloat16_as_ushort(l0) | ((uint32_t)__bfloat16_as_ushort(l1) << 16);
    }
    *reinterpret_cast<uint4*>(&g_Xh[i]) = make_uint4(ph[0], ph[1], ph[2], ph[3]);
    *reinterpret_cast<uint4*>(&g_Xl[i]) = make_uint4(pl[0], pl[1], pl[2], pl[3]);
}

// ---------------------------------------------------------------------------
// Setup: one block per mixture component k; writes transposed bf16 hi/lo
// B = [G | H] plus c, Ck, ip.
// ---------------------------------------------------------------------------
__global__ void __launch_bounds__(256) setup_kernel(
    const float* __restrict__ log_pi,
    const float* __restrict__ mu,
    const float* __restrict__ Lambda,
    const float* __restrict__ log_psi)
{
    __shared__ float Ls[DD][QQ + 1];
    __shared__ float LsW[DD][QQ + 1];
    __shared__ float Msm[QQ][QQ + 1];
    __shared__ float Lch[QQ][QQ + 1];
    __shared__ float invd_s[QQ];
    __shared__ float c_s[QQ];
    __shared__ float s_mdm, s_ldpsi, s_ldM;

    const int k = blockIdx.x;
    const int t = threadIdx.x;
    const int lane = t & 31;
    const int w = t >> 5;

    float psi = __expf(log_psi[t]) + 1e-6f + 1e-5f;
    float ip = 1.0f / psi;

    if (t == 0) { s_mdm = 0.f; s_ldpsi = 0.f; }
    if (t < QQ) c_s[t] = 0.f;

    {
        const float4* lp = reinterpret_cast<const float4*>(Lambda + ((size_t)k * DD + t) * QQ);
        float4 v0 = lp[0], v1 = lp[1], v2 = lp[2], v3 = lp[3];
        float vv[QQ] = {v0.x,v0.y,v0.z,v0.w, v1.x,v1.y,v1.z,v1.w,
                        v2.x,v2.y,v2.z,v2.w, v3.x,v3.y,v3.z,v3.w};
        #pragma unroll
        for (int i = 0; i < QQ; i++) { Ls[t][i] = vv[i]; LsW[t][i] = ip * vv[i]; }
    }
    __syncthreads();

    {
        float v = warp_sum(__logf(psi));
        if (lane == 0) atomicAdd(&s_ldpsi, v);
    }

    {
        int q1 = t >> 4, q2 = t & 15;
        float s0 = 0.f, s1 = 0.f, s2 = 0.f, s3 = 0.f;
        #pragma unroll 4
        for (int d = 0; d < DD; d += 4) {
            s0 = fmaf(LsW[d + 0][q1], Ls[d + 0][q2], s0);
            s1 = fmaf(LsW[d + 1][q1], Ls[d + 1][q2], s1);
            s2 = fmaf(LsW[d + 2][q1], Ls[d + 2][q2], s2);
            s3 = fmaf(LsW[d + 3][q1], Ls[d + 3][q2], s3);
        }
        Msm[q1][q2] = (s0 + s1) + (s2 + s3) + (q1 == q2 ? 1.0f : 0.0f);
    }
    __syncthreads();

    if (w == 0) {  // warp-parallel Cholesky (16x16)
        float W[QQ];
        #pragma unroll
        for (int j = 0; j < QQ; j++) W[j] = (lane < QQ) ? Msm[lane][j] : 0.f;
        float myd = 1.0f;
        #pragma unroll
        for (int j = 0; j < QQ; j++) {
            float pivot = __shfl_sync(0xffffffffu, W[j], j);
            float rs = rsqrtf(pivot);
            float ljj = pivot * rs;
            float lij;
            if (lane == j)                  { lij = ljj; myd = ljj; invd_s[j] = rs; }
            else if (lane > j && lane < QQ) { lij = W[j] * rs; }
            else                            { lij = 0.f; }
            if (lane < QQ) Lch[lane][j] = lij;
            #pragma unroll
            for (int p = j + 1; p < QQ; p++) {
                float lpj = __shfl_sync(0xffffffffu, lij, p);
                W[p] = fmaf(-lij, lpj, W[p]);
            }
        }
        float ldm = warp_sum(__logf(myd));
        if (lane == 0) s_ldM = 2.0f * ldm;
    }
    __syncthreads();

    {
        float g[QQ];
        #pragma unroll
        for (int i = 0; i < QQ; i++) {
            float v = LsW[t][i];
            #pragma unroll
            for (int p = 0; p < QQ; p++)
                if (p < i) v = fmaf(-Lch[i][p], g[p], v);
            g[i] = v * invd_s[i];
        }
        float mud = mu[(size_t)k * DD + t];

        // transposed bf16 hi/lo writes: B[col][d], col = k*16+i for G, 512+k for H
        #pragma unroll
        for (int i = 0; i < QQ; i++) {
            __nv_bfloat16 h = __float2bfloat16(g[i]);
            g_Bh[(size_t)(k * QQ + i) * DD + t] = h;
            g_Bl[(size_t)(k * QQ + i) * DD + t] = __float2bfloat16(g[i] - __bfloat162float(h));
        }
        {
            float hv = ip * mud;
            __nv_bfloat16 h = __float2bfloat16(hv);
            g_Bh[(size_t)(512 + k) * DD + t] = h;
            g_Bl[(size_t)(512 + k) * DD + t] = __float2bfloat16(hv - __bfloat162float(h));
        }
        if (k == 0) g_ip[t] = ip;

        #pragma unroll
        for (int i = 0; i < QQ; i++) {
            float v = warp_sum(g[i] * mud);
            if (lane == 0) atomicAdd(&c_s[i], v);
        }
        float vm = warp_sum(ip * mud * mud);
        if (lane == 0) atomicAdd(&s_mdm, vm);
    }
    __syncthreads();

    if (t < QQ) g_c[k * QQ + t] = c_s[t];
    if (t == 0) {
        const float LOG2PI = 1.8378770664093453f;
        g_Ck[k] = log_pi[k] - 0.5f * ((float)DD * LOG2PI + s_ldpsi + s_ldM + s_mdm);
    }
}

// ---------------------------------------------------------------------------
// HMMA GEMM (mma.sync bf16, baseline PTX — no 'a'-ISA needed):
// D[128x128] fp32 = Xh@Bh^T + Xh@Bl^T + Xl@Bh^T over K=256.
// 8 warps, warp tile m64 x n32 (4x4 m16n8 frags). Double-buffered K=32 stages.
// Smem rows padded to 80B -> conflict-free ldmatrix.
// Fused epilogue: P = ||u-c||^2 (col tiles 0..3) / HX (col tile 4).
// ---------------------------------------------------------------------------
#define MATB 10240              // 128 rows * 80B
#define STAGEB (4 * MATB)       // Ah, Al, Bh, Bl
#define GEMM_SMEM (2 * STAGEB)  // 81920B

__global__ void __launch_bounds__(256, 1) gemm_kernel()
{
    extern __shared__ char smem[];
    const uint32_t sb = smem_u32(smem);
    __shared__ float csm2[128];

    const int tid = threadIdx.x;
    const int wid = tid >> 5;
    const int lane = tid & 31;
    const int wr = wid & 1;          // m half (64 rows)
    const int wc = wid >> 1;         // n quarter (32 cols)
    const int rowBase = blockIdx.x * 128;
    const int colBase = blockIdx.y * 128;
    const int colTile = blockIdx.y;

    if (colTile < 4 && tid < 128) csm2[tid] = g_c[colBase + tid];

    float acc[4][4][4];
    #pragma unroll
    for (int mt = 0; mt < 4; mt++)
        #pragma unroll
        for (int nt = 0; nt < 4; nt++)
            #pragma unroll
            for (int c = 0; c < 4; c++) acc[mt][nt][c] = 0.f;

    // global -> smem stage loader (rows padded to 80B)
    auto load_stage = [&](int s) {
        const int kbase = s * 32;
        char* buf = smem + (s & 1) * STAGEB;
        #pragma unroll
        for (int tl = 0; tl < 4; tl++) {
            const __nv_bfloat16* src = (tl == 0) ? g_Xh : (tl == 1) ? g_Xl
                                     : (tl == 2) ? g_Bh : g_Bl;
            const int rbase = (tl < 2) ? rowBase : colBase;
            char* dst = buf + tl * MATB;
            #pragma unroll
            for (int i = 0; i < 2; i++) {
                int idx = tid + i * 256;          // 0..511
                int row = idx >> 2, quad = idx & 3;
                uint4 v = *reinterpret_cast<const uint4*>(
                    src + (size_t)(rbase + row) * DD + kbase + quad * 8);
                *reinterpret_cast<uint4*>(dst + row * 80 + quad * 16) = v;
            }
        }
    };

    load_stage(0);
    __syncthreads();

    for (int s = 0; s < 8; s++) {
        if (s < 7) load_stage(s + 1);

        const uint32_t base = sb + (s & 1) * STAGEB;
        const uint32_t Ah = base, Al = base + MATB;
        const uint32_t Bh = base + 2 * MATB, Bl = base + 3 * MATB;

        #pragma unroll
        for (int kk = 0; kk < 2; kk++) {
            uint32_t ah[4][4], al[4][4], bh[8], bl[8];

            // A frags: row = wr*64 + mt*16 + (lane&7) + ((lane>>3)&1)*8
            //          kcol = kk*16 + ((lane>>4)&1)*8
            {
                int row0 = wr * 64 + (lane & 7) + ((lane >> 3) & 1) * 8;
                int kcol = kk * 16 + ((lane >> 4) & 1) * 8;
                uint32_t off = (uint32_t)(row0 * 80 + kcol * 2);
                #pragma unroll
                for (int mt = 0; mt < 4; mt++) {
                    LDM_X4(ah[mt], Ah + off + mt * (16 * 80));
                    LDM_X4(al[mt], Al + off + mt * (16 * 80));
                }
            }
            // B frags: n = wc*32 + ntp*16 + ((lane>>4)&1)*8 + (lane&7)
            //          kb = kk*16 + ((lane>>3)&1)*8
            {
                int n0 = wc * 32 + ((lane >> 4) & 1) * 8 + (lane & 7);
                int kb = kk * 16 + ((lane >> 3) & 1) * 8;
                uint32_t off = (uint32_t)(n0 * 80 + kb * 2);
                LDM_X4(&bh[0], Bh + off);
                LDM_X4(&bh[4], Bh + off + 16 * 80);
                LDM_X4(&bl[0], Bl + off);
                LDM_X4(&bl[4], Bl + off + 16 * 80);
            }

            #pragma unroll
            for (int mt = 0; mt < 4; mt++)
                #pragma unroll
                for (int nt = 0; nt < 4; nt++) {
                    mma_bf16(acc[mt][nt], ah[mt], &bh[nt * 2]);
                    mma_bf16(acc[mt][nt], ah[mt], &bl[nt * 2]);
                    mma_bf16(acc[mt][nt], al[mt], &bh[nt * 2]);
                }
        }
        __syncthreads();
    }

    // Epilogue
    if (colTile < 4) {
        #pragma unroll
        for (int mt = 0; mt < 4; mt++) {
            int r1 = rowBase + wr * 64 + mt * 16 + (lane >> 2);
            #pragma unroll
            for (int kp = 0; kp < 2; kp++) {
                float p0 = 0.f, p1 = 0.f;
                #pragma unroll
                for (int half = 0; half < 2; half++) {
                    int nt = kp * 2 + half;
                    int gc = wc * 32 + nt * 8 + 2 * (lane & 3);
                    float cc0 = csm2[gc], cc1 = csm2[gc + 1];
                    float e;
                    e = acc[mt][nt][0] - cc0; p0 = fmaf(e, e, p0);
                    e = acc[mt][nt][1] - cc1; p0 = fmaf(e, e, p0);
                    e = acc[mt][nt][2] - cc0; p1 = fmaf(e, e, p1);
                    e = acc[mt][nt][3] - cc1; p1 = fmaf(e, e, p1);
                }
                p0 += __shfl_xor_sync(0xffffffffu, p0, 1);
                p0 += __shfl_xor_sync(0xffffffffu, p0, 2);
                p1 += __shfl_xor_sync(0xffffffffu, p1, 1);
                p1 += __shfl_xor_sync(0xffffffffu, p1, 2);
                if ((lane & 3) == 0) {
                    int kg = (colBase >> 4) + wc * 2 + kp;
                    g_P[(size_t)r1 * KK + kg] = p0;
                    g_P[(size_t)(r1 + 8) * KK + kg] = p1;
                }
            }
        }
    } else if (wc == 0) {
        // H tile: cols 0..31 are the K columns of H
        #pragma unroll
        for (int mt = 0; mt < 4; mt++) {
            int r1 = rowBase + wr * 64 + mt * 16 + (lane >> 2);
            #pragma unroll
            for (int nt = 0; nt < 4; nt++) {
                int col = nt * 8 + 2 * (lane & 3);
                float2 v0 = make_float2(acc[mt][nt][0], acc[mt][nt][1]);
                float2 v1 = make_float2(acc[mt][nt][2], acc[mt][nt][3]);
                *reinterpret_cast<float2*>(&g_HX[(size_t)r1 * KK + col]) = v0;
                *reinterpret_cast<float2*>(&g_HX[(size_t)(r1 + 8) * KK + col]) = v1;
            }
        }
    }
}

// ---------------------------------------------------------------------------
// Epilogue: per row n, xdx = x^T Psi^-1 x, combine with P and HX, log-softmax.
// ---------------------------------------------------------------------------
__global__ void __launch_bounds__(256) epi_kernel(
    const float* __restrict__ X, float* __restrict__ out)
{
    __shared__ float Cks[KK];
    __shared__ unsigned long long ips2[DD / 2];

    const int tid = threadIdx.x;
    const int w = tid >> 5;
    const int lane = tid & 31;

    if (tid < KK) Cks[tid] = g_Ck[tid];
    if (tid < DD / 2) {
        unsigned long long p;
        PACK2(p, g_ip[2 * tid], g_ip[2 * tid + 1]);
        ips2[tid] = p;
    }
    __syncthreads();

    #pragma unroll 1
    for (int it = 0; it < 8; it++) {
        int n = blockIdx.x * 64 + it * 8 + w;

        unsigned long long xdx2 = 0ULL;
        #pragma unroll
        for (int j = 0; j < 4; j++) {
            int m = j * 32 + lane;
            unsigned long long xp = *reinterpret_cast<const unsigned long long*>(
                &X[(size_t)n * DD + 2 * m]);
            unsigned long long t2;
            MUL2(t2, ips2[m], xp);
            FMA2(xdx2, t2, xp);
        }
        float xlo, xhi;
        UNPACK2(xlo, xhi, xdx2);
        float xdx = warp_sum(xlo + xhi);

        float val = Cks[lane] + g_HX[(size_t)n * KK + lane]
                  + 0.5f * g_P[(size_t)n * KK + lane] - 0.5f * xdx;

        float m = warp_max(val);
        float s = warp_sum(__expf(val - m));
        float lse = m + __logf(s);

        out[(size_t)n * KK + lane] = val - lse;
        if (lane == 0) out[(size_t)NN * KK + n] = lse;
        __syncwarp();
    }
}

extern "C" void kernel_launch(void* const* d_in, const int* in_sizes, int n_in,
                              void* d_out, int out_size)
{
    const float* X       = (const float*)d_in[0];
    const float* log_pi  = (const float*)d_in[1];
    const float* mu      = (const float*)d_in[2];
    const float* Lambda  = (const float*)d_in[3];
    const float* log_psi = (const float*)d_in[4];
    float* out = (float*)d_out;

    cudaFuncSetAttribute(gemm_kernel, cudaFuncAttributeMaxDynamicSharedMemorySize, GEMM_SMEM);

    convx_kernel<<<NN * DD / 2048, 256>>>(X);
    setup_kernel<<<KK, 256>>>(log_pi, mu, Lambda, log_psi);
    gemm_kernel<<<dim3(NN / 128, 5), 256, GEMM_SMEM>>>();
    epi_kernel<<<NN / 64, 256>>>(X, out);
}

// round 13
// speedup vs baseline: 2.1685x; 1.2797x over previous
#include <stdint.h>
#include <cstdint>
#include <cuda_runtime.h>
#include <cuda_bf16.h>
#include <math.h>

#define DD 256
#define KK 32
#define QQ 16
#define NN 8192
#define NCOL 544          // 512 G cols + 32 H cols

// Scratch (device globals: no allocation allowed in kernel_launch)
__device__ float g_c[KK * QQ];            // c_k = G_k^T mu_k
__device__ float g_Ck[KK];                // per-k constant
__device__ float g_P[NN * KK];            // ||G^T x - c||^2
__device__ float g_HX[NN * KK];           // h_k^T x
__device__ float g_XDX[NN];               // x^T Psi^-1 x
__device__ __align__(16) __nv_bfloat16 g_Xh[NN * DD];
__device__ __align__(16) __nv_bfloat16 g_Xl[NN * DD];
__device__ __align__(16) __nv_bfloat16 g_Bh[NCOL * DD];   // [col][d]
__device__ __align__(16) __nv_bfloat16 g_Bl[NCOL * DD];

__device__ __forceinline__ uint32_t smem_u32(const void* p) {
    uint32_t a;
    asm("{ .reg .u64 t; cvta.to.shared.u64 t, %1; cvt.u32.u64 %0, t; }" : "=r"(a) : "l"(p));
    return a;
}

// ldmatrix x4 (baseline PTX, sm_75+)
#define LDM_X4(r, addr) \
    asm volatile("ldmatrix.sync.aligned.m8n8.x4.shared.b16 {%0,%1,%2,%3}, [%4];" \
        : "=r"((r)[0]), "=r"((r)[1]), "=r"((r)[2]), "=r"((r)[3]) : "r"(addr))

// mma.sync bf16 (baseline PTX, sm_80+) — tensor pipe (HMMA)
__device__ __forceinline__ void mma_bf16(float* c, const uint32_t* a, const uint32_t* b) {
    asm volatile(
        "mma.sync.aligned.m16n8k16.row.col.f32.bf16.bf16.f32 "
        "{%0,%1,%2,%3}, {%4,%5,%6,%7}, {%8,%9}, {%0,%1,%2,%3};"
        : "+f"(c[0]), "+f"(c[1]), "+f"(c[2]), "+f"(c[3])
        : "r"(a[0]), "r"(a[1]), "r"(a[2]), "r"(a[3]), "r"(b[0]), "r"(b[1]));
}

__device__ __forceinline__ float warp_sum(float v) {
    v += __shfl_xor_sync(0xffffffffu, v, 16);
    v += __shfl_xor_sync(0xffffffffu, v, 8);
    v += __shfl_xor_sync(0xffffffffu, v, 4);
    v += __shfl_xor_sync(0xffffffffu, v, 2);
    v += __shfl_xor_sync(0xffffffffu, v, 1);
    return v;
}
__device__ __forceinline__ float warp_max(float v) {
    v = fmaxf(v, __shfl_xor_sync(0xffffffffu, v, 16));
    v = fmaxf(v, __shfl_xor_sync(0xffffffffu, v, 8));
    v = fmaxf(v, __shfl_xor_sync(0xffffffffu, v, 4));
    v = fmaxf(v, __shfl_xor_sync(0xffffffffu, v, 2));
    v = fmaxf(v, __shfl_xor_sync(0xffffffffu, v, 1));
    return v;
}

// ---------------------------------------------------------------------------
// Fused pre-pass. Blocks < 1024: X convert (bf16 hi/lo) + xdx reduction
// (one warp per row). Blocks 1024..1055: per-k setup (M, Cholesky, G, H, c, Ck).
// The streaming convert blocks overlap the latency-bound setup blocks.
// ---------------------------------------------------------------------------
__global__ void __launch_bounds__(256) pre_kernel(
    const float* __restrict__ X,
    const float* __restrict__ log_pi,
    const float* __restrict__ mu,
    const float* __restrict__ Lambda,
    const float* __restrict__ log_psi)
{
    __shared__ float Ls[DD][QQ + 1];
    __shared__ float LsW[DD][QQ + 1];
    __shared__ float Msm[QQ][QQ + 1];
    __shared__ float Lch[QQ][QQ + 1];
    __shared__ float invd_s[QQ];
    __shared__ float c_s[QQ];
    __shared__ float s_mdm, s_ldpsi, s_ldM;

    const int t = threadIdx.x;
    const int lane = t & 31;
    const int w = t >> 5;

    if (blockIdx.x < 1024) {
        // ---- X convert + xdx ----
        int i = (blockIdx.x * 256 + t) * 8;
        float4 a = *reinterpret_cast<const float4*>(X + i);
        float4 b = *reinterpret_cast<const float4*>(X + i + 4);
        float v[8] = {a.x, a.y, a.z, a.w, b.x, b.y, b.z, b.w};

        // inv_psi for this thread's 8 dims: d = lane*8 + j
        float xpart = 0.f;
        #pragma unroll
        for (int j = 0; j < 8; j++) {
            float psi = __expf(log_psi[lane * 8 + j]) + 1e-6f + 1e-5f;
            xpart = fmaf(v[j] * v[j], 1.0f / psi, xpart);
        }
        float xdx = warp_sum(xpart);
        if (lane == 0) g_XDX[blockIdx.x * 8 + w] = xdx;

        uint32_t ph[4], pl[4];
        #pragma unroll
        for (int j = 0; j < 4; j++) {
            __nv_bfloat16 h0 = __float2bfloat16(v[2 * j]);
            __nv_bfloat16 h1 = __float2bfloat16(v[2 * j + 1]);
            __nv_bfloat16 l0 = __float2bfloat16(v[2 * j] - __bfloat162float(h0));
            __nv_bfloat16 l1 = __float2bfloat16(v[2 * j + 1] - __bfloat162float(h1));
            ph[j] = (uint32_t)__bfloat16_as_ushort(h0) | ((uint32_t)__bfloat16_as_ushort(h1) << 16);
            pl[j] = (uint32_t)__bfloat16_as_ushort(l0) | ((uint32_t)__bfloat16_as_ushort(l1) << 16);
        }
        *reinterpret_cast<uint4*>(&g_Xh[i]) = make_uint4(ph[0], ph[1], ph[2], ph[3]);
        *reinterpret_cast<uint4*>(&g_Xl[i]) = make_uint4(pl[0], pl[1], pl[2], pl[3]);
        return;
    }

    // ---- setup for component k ----
    const int k = blockIdx.x - 1024;

    float psi = __expf(log_psi[t]) + 1e-6f + 1e-5f;
    float ip = 1.0f / psi;

    if (t == 0) { s_mdm = 0.f; s_ldpsi = 0.f; }
    if (t < QQ) c_s[t] = 0.f;

    {
        const float4* lp = reinterpret_cast<const float4*>(Lambda + ((size_t)k * DD + t) * QQ);
        float4 v0 = lp[0], v1 = lp[1], v2 = lp[2], v3 = lp[3];
        float vv[QQ] = {v0.x,v0.y,v0.z,v0.w, v1.x,v1.y,v1.z,v1.w,
                        v2.x,v2.y,v2.z,v2.w, v3.x,v3.y,v3.z,v3.w};
        #pragma unroll
        for (int i = 0; i < QQ; i++) { Ls[t][i] = vv[i]; LsW[t][i] = ip * vv[i]; }
    }
    __syncthreads();

    {
        float v = warp_sum(__logf(psi));
        if (lane == 0) atomicAdd(&s_ldpsi, v);
    }

    {
        int q1 = t >> 4, q2 = t & 15;
        float s0 = 0.f, s1 = 0.f, s2 = 0.f, s3 = 0.f;
        #pragma unroll 4
        for (int d = 0; d < DD; d += 4) {
            s0 = fmaf(LsW[d + 0][q1], Ls[d + 0][q2], s0);
            s1 = fmaf(LsW[d + 1][q1], Ls[d + 1][q2], s1);
            s2 = fmaf(LsW[d + 2][q1], Ls[d + 2][q2], s2);
            s3 = fmaf(LsW[d + 3][q1], Ls[d + 3][q2], s3);
        }
        Msm[q1][q2] = (s0 + s1) + (s2 + s3) + (q1 == q2 ? 1.0f : 0.0f);
    }
    __syncthreads();

    if (w == 0) {  // warp-parallel Cholesky (16x16)
        float W[QQ];
        #pragma unroll
        for (int j = 0; j < QQ; j++) W[j] = (lane < QQ) ? Msm[lane][j] : 0.f;
        float myd = 1.0f;
        #pragma unroll
        for (int j = 0; j < QQ; j++) {
            float pivot = __shfl_sync(0xffffffffu, W[j], j);
            float rs = rsqrtf(pivot);
            float ljj = pivot * rs;
            float lij;
            if (lane == j)                  { lij = ljj; myd = ljj; invd_s[j] = rs; }
            else if (lane > j && lane < QQ) { lij = W[j] * rs; }
            else                            { lij = 0.f; }
            if (lane < QQ) Lch[lane][j] = lij;
            #pragma unroll
            for (int p = j + 1; p < QQ; p++) {
                float lpj = __shfl_sync(0xffffffffu, lij, p);
                W[p] = fmaf(-lij, lpj, W[p]);
            }
        }
        float ldm = warp_sum(__logf(myd));
        if (lane == 0) s_ldM = 2.0f * ldm;
    }
    __syncthreads();

    {
        float g[QQ];
        #pragma unroll
        for (int i = 0; i < QQ; i++) {
            float v = LsW[t][i];
            #pragma unroll
            for (int p = 0; p < QQ; p++)
                if (p < i) v = fmaf(-Lch[i][p], g[p], v);
            g[i] = v * invd_s[i];
        }
        float mud = mu[(size_t)k * DD + t];

        // transposed bf16 hi/lo: B[col][d], col = k*16+i for G, 512+k for H
        #pragma unroll
        for (int i = 0; i < QQ; i++) {
            __nv_bfloat16 h = __float2bfloat16(g[i]);
            g_Bh[(size_t)(k * QQ + i) * DD + t] = h;
            g_Bl[(size_t)(k * QQ + i) * DD + t] = __float2bfloat16(g[i] - __bfloat162float(h));
        }
        {
            float hv = ip * mud;
            __nv_bfloat16 h = __float2bfloat16(hv);
            g_Bh[(size_t)(512 + k) * DD + t] = h;
            g_Bl[(size_t)(512 + k) * DD + t] = __float2bfloat16(hv - __bfloat162float(h));
        }

        #pragma unroll
        for (int i = 0; i < QQ; i++) {
            float v = warp_sum(g[i] * mud);
            if (lane == 0) atomicAdd(&c_s[i], v);
        }
        float vm = warp_sum(ip * mud * mud);
        if (lane == 0) atomicAdd(&s_mdm, vm);
    }
    __syncthreads();

    if (t < QQ) g_c[k * QQ + t] = c_s[t];
    if (t == 0) {
        const float LOG2PI = 1.8378770664093453f;
        g_Ck[k] = log_pi[k] - 0.5f * ((float)DD * LOG2PI + s_ldpsi + s_ldM + s_mdm);
    }
}

// ---------------------------------------------------------------------------
// HMMA GEMM: D = Xh@Bh^T + Xh@Bl^T + Xl@Bh^T over K=256.
// Col tiles 0..3: N=128 (G cols), 8 warps m64 x n32, fused P = ||u-c||^2.
// Col tile 4:     N=32  (H cols), 8 warps m16 x n32, writes HX.
// Double-buffered K=32 stages, 80B-padded smem rows (conflict-free ldmatrix).
// ---------------------------------------------------------------------------
#define MATB 10240              // 128 rows * 80B
#define STAGEB (4 * MATB)       // Ah, Al, Bh, Bl
#define GEMM_SMEM (2 * STAGEB)  // 81920B

__global__ void __launch_bounds__(256, 1) gemm_kernel()
{
    extern __shared__ char smem[];
    const uint32_t sb = smem_u32(smem);
    __shared__ float csm2[128];

    const int tid = threadIdx.x;
    const int wid = tid >> 5;
    const int lane = tid & 31;
    const int rowBase = blockIdx.x * 128;
    const int colBase = blockIdx.y * 128;
    const int colTile = blockIdx.y;

    if (colTile < 4) {
        // ================= G tiles: N=128 =================
        const int wr = wid & 1;          // m half (64 rows)
        const int wc = wid >> 1;         // n quarter (32 cols)
        if (tid < 128) csm2[tid] = g_c[colBase + tid];

        float acc[4][4][4];
        #pragma unroll
        for (int mt = 0; mt < 4; mt++)
            #pragma unroll
            for (int nt = 0; nt < 4; nt++)
                #pragma unroll
                for (int c = 0; c < 4; c++) acc[mt][nt][c] = 0.f;

        auto load_stage = [&](int s) {
            const int kbase = s * 32;
            char* buf = smem + (s & 1) * STAGEB;
            #pragma unroll
            for (int tl = 0; tl < 4; tl++) {
                const __nv_bfloat16* src = (tl == 0) ? g_Xh : (tl == 1) ? g_Xl
                                         : (tl == 2) ? g_Bh : g_Bl;
                const int rbase = (tl < 2) ? rowBase : colBase;
                char* dst = buf + tl * MATB;
                #pragma unroll
                for (int i = 0; i < 2; i++) {
                    int idx = tid + i * 256;
                    int row = idx >> 2, quad = idx & 3;
                    uint4 v = *reinterpret_cast<const uint4*>(
                        src + (size_t)(rbase + row) * DD + kbase + quad * 8);
                    *reinterpret_cast<uint4*>(dst + row * 80 + quad * 16) = v;
                }
            }
        };

        load_stage(0);
        __syncthreads();

        for (int s = 0; s < 8; s++) {
            if (s < 7) load_stage(s + 1);
            const uint32_t base = sb + (s & 1) * STAGEB;
            const uint32_t Ah = base, Al = base + MATB;
            const uint32_t Bh = base + 2 * MATB, Bl = base + 3 * MATB;

            #pragma unroll
            for (int kk = 0; kk < 2; kk++) {
                uint32_t ah[4][4], al[4][4], bh[8], bl[8];
                {
                    int row0 = wr * 64 + (lane & 7) + ((lane >> 3) & 1) * 8;
                    int kcol = kk * 16 + ((lane >> 4) & 1) * 8;
                    uint32_t off = (uint32_t)(row0 * 80 + kcol * 2);
                    #pragma unroll
                    for (int mt = 0; mt < 4; mt++) {
                        LDM_X4(ah[mt], Ah + off + mt * (16 * 80));
                        LDM_X4(al[mt], Al + off + mt * (16 * 80));
                    }
                }
                {
                    int n0 = wc * 32 + ((lane >> 4) & 1) * 8 + (lane & 7);
                    int kb = kk * 16 + ((lane >> 3) & 1) * 8;
                    uint32_t off = (uint32_t)(n0 * 80 + kb * 2);
                    LDM_X4(&bh[0], Bh + off);
                    LDM_X4(&bh[4], Bh + off + 16 * 80);
                    LDM_X4(&bl[0], Bl + off);
                    LDM_X4(&bl[4], Bl + off + 16 * 80);
                }
                #pragma unroll
                for (int mt = 0; mt < 4; mt++)
                    #pragma unroll
                    for (int nt = 0; nt < 4; nt++) {
                        mma_bf16(acc[mt][nt], ah[mt], &bh[nt * 2]);
                        mma_bf16(acc[mt][nt], ah[mt], &bl[nt * 2]);
                        mma_bf16(acc[mt][nt], al[mt], &bh[nt * 2]);
                    }
            }
            __syncthreads();
        }

        #pragma unroll
        for (int mt = 0; mt < 4; mt++) {
            int r1 = rowBase + wr * 64 + mt * 16 + (lane >> 2);
            #pragma unroll
            for (int kp = 0; kp < 2; kp++) {
                float p0 = 0.f, p1 = 0.f;
                #pragma unroll
                for (int half = 0; half < 2; half++) {
                    int nt = kp * 2 + half;
                    int gc = wc * 32 + nt * 8 + 2 * (lane & 3);
                    float cc0 = csm2[gc], cc1 = csm2[gc + 1];
                    float e;
                    e = acc[mt][nt][0] - cc0; p0 = fmaf(e, e, p0);
                    e = acc[mt][nt][1] - cc1; p0 = fmaf(e, e, p0);
                    e = acc[mt][nt][2] - cc0; p1 = fmaf(e, e, p1);
                    e = acc[mt][nt][3] - cc1; p1 = fmaf(e, e, p1);
                }
                p0 += __shfl_xor_sync(0xffffffffu, p0, 1);
                p0 += __shfl_xor_sync(0xffffffffu, p0, 2);
                p1 += __shfl_xor_sync(0xffffffffu, p1, 1);
                p1 += __shfl_xor_sync(0xffffffffu, p1, 2);
                if ((lane & 3) == 0) {
                    int kg = (colBase >> 4) + wc * 2 + kp;
                    g_P[(size_t)r1 * KK + kg] = p0;
                    g_P[(size_t)(r1 + 8) * KK + kg] = p1;
                }
            }
        }
    } else {
        // ================= H tile: N=32 =================
        float acc[4][4];
        #pragma unroll
        for (int nt = 0; nt < 4; nt++)
            #pragma unroll
            for (int c = 0; c < 4; c++) acc[nt][c] = 0.f;

        auto load_stage4 = [&](int s) {
            const int kbase = s * 32;
            char* buf = smem + (s & 1) * STAGEB;
            // A tiles full 128 rows
            #pragma unroll
            for (int tl = 0; tl < 2; tl++) {
                const __nv_bfloat16* src = (tl == 0) ? g_Xh : g_Xl;
                char* dst = buf + tl * MATB;
                #pragma unroll
                for (int i = 0; i < 2; i++) {
                    int idx = tid + i * 256;
                    int row = idx >> 2, quad = idx & 3;
                    uint4 v = *reinterpret_cast<const uint4*>(
                        src + (size_t)(rowBase + row) * DD + kbase + quad * 8);
                    *reinterpret_cast<uint4*>(dst + row * 80 + quad * 16) = v;
                }
            }
            // B tiles: 32 rows only (H cols 512..543)
            {
                int idx = tid;             // 0..255 covers Bh (128) + Bl (128)
                int half = idx >> 7;       // 0: Bh, 1: Bl
                int r = (idx & 127) >> 2, quad = idx & 3;
                const __nv_bfloat16* src = half ? g_Bl : g_Bh;
                char* dst = buf + (2 + half) * MATB;
                uint4 v = *reinterpret_cast<const uint4*>(
                    src + (size_t)(512 + r) * DD + kbase + quad * 8);
                *reinterpret_cast<uint4*>(dst + r * 80 + quad * 16) = v;
            }
        };

        load_stage4(0);
        __syncthreads();

        for (int s = 0; s < 8; s++) {
            if (s < 7) load_stage4(s + 1);
            const uint32_t base = sb + (s & 1) * STAGEB;
            const uint32_t Ah = base, Al = base + MATB;
            const uint32_t Bh = base + 2 * MATB, Bl = base + 3 * MATB;

            #pragma unroll
            for (int kk = 0; kk < 2; kk++) {
                uint32_t ah[4], al[4], bh[8], bl[8];
                {
                    int row0 = wid * 16 + (lane & 7) + ((lane >> 3) & 1) * 8;
                    int kcol = kk * 16 + ((lane >> 4) & 1) * 8;
                    uint32_t off = (uint32_t)(row0 * 80 + kcol * 2);
                    LDM_X4(ah, Ah + off);
                    LDM_X4(al, Al + off);
                }
                {
                    int n0 = ((lane >> 4) & 1) * 8 + (lane & 7);
                    int kb = kk * 16 + ((lane >> 3) & 1) * 8;
                    uint32_t off = (uint32_t)(n0 * 80 + kb * 2);
                    LDM_X4(&bh[0], Bh + off);
                    LDM_X4(&bh[4], Bh + off + 16 * 80);
                    LDM_X4(&bl[0], Bl + off);
                    LDM_X4(&bl[4], Bl + off + 16 * 80);
                }
                #pragma unroll
                for (int nt = 0; nt < 4; nt++) {
                    mma_bf16(acc[nt], ah, &bh[nt * 2]);
                    mma_bf16(acc[nt], ah, &bl[nt * 2]);
                    mma_bf16(acc[nt], al, &bh[nt * 2]);
                }
            }
            __syncthreads();
        }

        int r1 = rowBase + wid * 16 + (lane >> 2);
        #pragma unroll
        for (int nt = 0; nt < 4; nt++) {
            int col = nt * 8 + 2 * (lane & 3);
            *reinterpret_cast<float2*>(&g_HX[(size_t)r1 * KK + col]) =
                make_float2(acc[nt][0], acc[nt][1]);
            *reinterpret_cast<float2*>(&g_HX[(size_t)(r1 + 8) * KK + col]) =
                make_float2(acc[nt][2], acc[nt][3]);
        }
    }
}

// ---------------------------------------------------------------------------
// Epilogue: combine precomputed P, HX, XDX, Ck; log-softmax over k.
// One warp per row; 8 warps x 4 rows per block; grid 256.
// ---------------------------------------------------------------------------
__global__ void __launch_bounds__(256) epi_kernel(float* __restrict__ out)
{
    const int tid = threadIdx.x;
    const int w = tid >> 5;
    const int lane = tid & 31;
    const float Ck = g_Ck[lane];

    #pragma unroll
    for (int it = 0; it < 4; it++) {
        int n = blockIdx.x * 32 + it * 8 + w;
        float xdx = g_XDX[n];
        float val = Ck + g_HX[(size_t)n * KK + lane]
                  + 0.5f * g_P[(size_t)n * KK + lane] - 0.5f * xdx;

        float m = warp_max(val);
        float s = warp_sum(__expf(val - m));
        float lse = m + __logf(s);

        out[(size_t)n * KK + lane] = val - lse;
        if (lane == 0) out[(size_t)NN * KK + n] = lse;
    }
}

extern "C" void kernel_launch(void* const* d_in, const int* in_sizes, int n_in,
                              void* d_out, int out_size)
{
    const float* X       = (const float*)d_in[0];
    const float* log_pi  = (const float*)d_in[1];
    const float* mu      = (const float*)d_in[2];
    const float* Lambda  = (const float*)d_in[3];
    const float* log_psi = (const float*)d_in[4];
    float* out = (float*)d_out;

    cudaFuncSetAttribute(gemm_kernel, cudaFuncAttributeMaxDynamicSharedMemorySize, GEMM_SMEM);

    pre_kernel<<<1024 + KK, 256>>>(X, log_pi, mu, Lambda, log_psi);
    gemm_kernel<<<dim3(NN / 128, 5), 256, GEMM_SMEM>>>();
    epi_kernel<<<NN / 32, 256>>>(out);
}